// round 12
// baseline (speedup 1.0000x reference)
#include <cuda_runtime.h>
#include <cuda_fp16.h>
#include <cstdint>

// CARAFE3D: x[2,32,32,32,32] -> out[2,16,64,64,64]
//   k_prep: W_enc -> fp16 mma-fragment-major (27 ntg); u16 region-offset tap table
//   k_down: t = W_down@x + b_down (8ch planar), z = W_out@x ([n][c/4][loc][4])
//   k_main: persistent fused kernel. Per 64-voxel tile:
//           MMA phase (W-resident, smem t-region, fp16 mma.sync, barrier-free)
//           -> enc exchanged via smem -> softmax + reassembly + pixel shuffle.
//           t-region and z-region register-prefetched under previous tile's MMA.
typedef unsigned long long ull;
typedef unsigned int u32;
typedef unsigned short u16;

#define VOX 32768
#define GV_TOTAL 65536
#define NTILES 1024            // 64 voxels per tile

__device__ float g_t[2 * 8 * VOX];
__device__ __align__(16) float g_z[2 * 16 * VOX];        // [n][c/4][loc][4]
__device__ __align__(16) uint2 g_wfrag[12096];           // [chunk14][ntg27][lane32]
__device__ u16 g_tapoff[224];

#define REG_N 3352             // t-region floats (3264 data + zero tail)

__device__ __forceinline__ ull dup2(float a) {
    ull r; unsigned u = __float_as_uint(a);
    asm("mov.b64 %0, {%1, %1};" : "=l"(r) : "r"(u));
    return r;
}
__device__ __forceinline__ ull pack2(float a, float b) {
    ull r;
    asm("mov.b64 %0, {%1, %2};" : "=l"(r) : "r"(__float_as_uint(a)), "r"(__float_as_uint(b)));
    return r;
}
__device__ __forceinline__ ull ffma2(ull a, ull b, ull c) {
    ull d;
    asm("fma.rn.f32x2 %0, %1, %2, %3;" : "=l"(d) : "l"(a), "l"(b), "l"(c));
    return d;
}
#define MMA_F16(d, a, b0_, b1_) \
    asm volatile("mma.sync.aligned.m16n8k16.row.col.f32.f16.f16.f32 " \
        "{%0,%1,%2,%3}, {%4,%5,%6,%7}, {%8,%9}, {%0,%1,%2,%3};" \
        : "+f"((d)[0]), "+f"((d)[1]), "+f"((d)[2]), "+f"((d)[3]) \
        : "r"((a)[0]), "r"((a)[1]), "r"((a)[2]), "r"((a)[3]), "r"(b0_), "r"(b1_))

__device__ __forceinline__ unsigned short f16bits(float v) {
    __half h = __float2half_rn(v);
    return *(unsigned short*)&h;
}
__device__ __forceinline__ u32 h2pack(float a, float b) {
    __half2 h = __floats2half2_rn(a, b);     // low = a
    return *(u32*)&h;
}

// ---------------- k_prep ----------------
__global__ void k_prep(const float* __restrict__ w_enc) {
    int i = blockIdx.x * 256 + threadIdx.x;
    if (i < 12096) {
        int chunk = i / 864;
        int rem = i - chunk * 864;
        int ntg = rem >> 5;
        int lane = rem & 31;
        int g = lane >> 2, tc = lane & 3;
        int oc = ntg * 8 + g;
        int kb = chunk * 16;
        int ks[4] = { kb + 2 * tc, kb + 2 * tc + 1, kb + 8 + 2 * tc, kb + 9 + 2 * tc };
        unsigned short hh[4];
#pragma unroll
        for (int j = 0; j < 4; j++) {
            float v = (ks[j] < 216) ? w_enc[oc * 216 + ks[j]] : 0.f;
            hh[j] = f16bits(v);
        }
        uint2 q;
        q.x = (u32)hh[0] | ((u32)hh[1] << 16);
        q.y = (u32)hh[2] | ((u32)hh[3] << 16);
        g_wfrag[i] = q;
    }
    if (i < 224) {
        if (i < 216) {
            int ci = i / 27;
            int tap = i - ci * 27;
            int th = tap / 9;
            int tr = tap - th * 9;
            int tw = tr / 3;
            int td = tr - tw * 3;
            g_tapoff[i] = (u16)((((ci * 3 + th) * 4 + tw) * 34) + td);
        } else {
            g_tapoff[i] = (u16)3264;
        }
    }
}

// ---------------- k_down ----------------
__global__ __launch_bounds__(256) void k_down(
    const float* __restrict__ x,
    const float* __restrict__ wd, const float* __restrict__ bd,
    const float* __restrict__ wo)
{
    __shared__ float swd[8 * 32];
    __shared__ float swo[16 * 32];
    int tid = threadIdx.x;
    if (tid < 256) swd[tid] = wd[tid];
    swo[tid] = wo[tid];
    swo[tid + 256] = wo[tid + 256];
    __syncthreads();

    int gv = blockIdx.x * 256 + tid;
    int n = gv >> 15;
    int loc = gv & (VOX - 1);
    const float* xb = x + n * (32 * VOX) + loc;

    float xv[32];
#pragma unroll
    for (int c = 0; c < 32; c++) xv[c] = xb[c * VOX];
#pragma unroll
    for (int m = 0; m < 8; m++) {
        float acc = bd[m];
#pragma unroll
        for (int c = 0; c < 32; c++) acc += swd[m * 32 + c] * xv[c];
        g_t[(n * 8 + m) * VOX + loc] = acc;
    }
    float za[16];
#pragma unroll
    for (int m = 0; m < 16; m++) {
        float acc = 0.f;
#pragma unroll
        for (int c = 0; c < 32; c++) acc += swo[m * 32 + c] * xv[c];
        za[m] = acc;
    }
#pragma unroll
    for (int cg = 0; cg < 4; cg++)
        *(float4*)(g_z + ((size_t)(n * 4 + cg) * VOX + loc) * 4) =
            make_float4(za[cg * 4], za[cg * 4 + 1], za[cg * 4 + 2], za[cg * 4 + 3]);
}

// ---------------- k_main: fused enc GEMM + softmax + reassembly ----------------
// Smem layout (bytes):
//   [0, 96768)        W fragments
//   [96768, +448)     tap offsets
//   [97216, +13408)   t region (im2col source)
//   [110624, +32640)  z region [12 row][34 d][pad20] x 16c
//   [143264, +56160)  enc exchange [54 grp][stride 260 words]
#define W_OFF 0
#define TAP_OFF 96768
#define REGION_OFF 97216
#define ZS_OFF 110624
#define ENC_OFF 143264
#define SMEM_MAIN 199424
#define ENC_STRIDE 260

__device__ __forceinline__ float region_val(int idx, int h, int w0, int base_t) {
    if (idx >= 3264) return 0.f;
    int ci = idx / 408;
    int r1 = idx - ci * 408;
    int hh = r1 / 136;
    int r2 = r1 - hh * 136;
    int ww = r2 / 34;
    int dd = r2 - ww * 34;
    int hs = h + hh - 1, ws = w0 + ww - 1, ds = dd - 1;
    if ((unsigned)hs < 32u && (unsigned)ws < 32u && (unsigned)ds < 32u)
        return g_t[base_t + ci * VOX + (hs << 10) + (ws << 5) + ds];
    return 0.f;
}

__device__ __forceinline__ float4 z_val(int idx, int h, int w0, const float* zbase) {
    // idx in [0,1632): [row 12][cg 4][dd 34]
    int row = idx / 136;
    int r = idx - row * 136;
    int cg = r / 34;
    int dd = r - cg * 34;
    int hh = row >> 2, ww = row & 3;
    int hs = h + hh - 1, ws = w0 + ww - 1, ds = dd - 1;
    if ((unsigned)hs < 32u && (unsigned)ws < 32u && (unsigned)ds < 32u)
        return *(const float4*)(zbase + ((size_t)cg * VOX + (hs << 10) + (ws << 5) + ds) * 4);
    return make_float4(0.f, 0.f, 0.f, 0.f);
}

__global__ __launch_bounds__(256, 1) void k_main(const float* __restrict__ b_enc,
                                                 const float* __restrict__ b_out,
                                                 float* __restrict__ out)
{
    extern __shared__ __align__(16) char smem[];
    float* region = (float*)(smem + REGION_OFF);
    float* zs = (float*)(smem + ZS_OFF);
    float* enc_s = (float*)(smem + ENC_OFF);
    const u16* s_tap = (const u16*)(smem + TAP_OFF);
    int tid = threadIdx.x;

    {
        uint2* wdst = (uint2*)(smem + W_OFF);
        for (int i = tid; i < 12096; i += 256) wdst[i] = g_wfrag[i];
    }
    if (tid < 224) ((u16*)(smem + TAP_OFF))[tid] = g_tapoff[tid];

    int warp = tid >> 5, lane = tid & 31;
    int warp_m = warp & 3;
    int warp_n = warp >> 2;
    int g = lane >> 2, tc = lane & 3;
    int nts = warp_n ? 13 : 14;

    int vA = warp_m * 16 + g;
    int vB = vA + 8;
    int aoffA = (vA >> 5) * 34 + (vA & 31);
    int aoffB = (vB >> 5) * 34 + (vB & 31);

    // out-phase thread mapping: 4 threads per voxel
    int vloc = tid & 63;
    int t2 = tid >> 6;
    int qh2 = t2 & 1;          // rh: r 0..3 vs 4..7
    int cgh = t2 >> 1;         // channels 0..7 vs 8..15
    int wv = vloc >> 5, dv = vloc & 31;

    float bo[8];
#pragma unroll
    for (int c8 = 0; c8 < 8; c8++) bo[c8] = __ldg(b_out + cgh * 8 + c8);

    // prefetch first tile
    int tile = blockIdx.x;
    float rv[14];
    float4 zv[7];
    {
        int loc0 = (tile * 64) & (VOX - 1);
        int h = loc0 >> 10, w0 = (loc0 >> 5) & 31;
        int nn = (tile * 64) >> 15;
        int base_t = nn * 8 * VOX;
        const float* zbase = g_z + (size_t)nn * (16 * VOX);
#pragma unroll
        for (int it = 0; it < 14; it++) {
            int idx = tid + it * 256;
            rv[it] = (idx < REG_N) ? region_val(idx, h, w0, base_t) : 0.f;
        }
#pragma unroll
        for (int it = 0; it < 7; it++) {
            int idx = tid + it * 256;
            zv[it] = (idx < 1632) ? z_val(idx, h, w0, zbase)
                                  : make_float4(0.f, 0.f, 0.f, 0.f);
        }
    }

    for (; tile < NTILES; tile += gridDim.x) {
        int gv0 = tile * 64;
        int n = gv0 >> 15;
        int loc0 = gv0 & (VOX - 1);
        int h = loc0 >> 10;
        int w0 = (loc0 >> 5) & 31;

        __syncthreads();           // all smem regions free
        // stage prefetched t-region and z-region
#pragma unroll
        for (int it = 0; it < 14; it++) {
            int idx = tid + it * 256;
            if (idx < REG_N) region[idx] = rv[it];
        }
#pragma unroll
        for (int it = 0; it < 7; it++) {
            int idx = tid + it * 256;
            if (idx < 1632) {
                int row = idx / 136;
                int r = idx - row * 136;
                int cg = r / 34;
                int dd = r - cg * 34;
                *(float4*)(zs + (row * 34 + dd) * 20 + cg * 4) = zv[it];
            }
        }
        __syncthreads();           // regions ready

        // prefetch next tile under the MMA mainloop
        int ntile = tile + gridDim.x;
        if (ntile < NTILES) {
            int nloc0 = (ntile * 64) & (VOX - 1);
            int nh = nloc0 >> 10, nw0 = (nloc0 >> 5) & 31;
            int nn = (ntile * 64) >> 15;
            int nbase_t = nn * 8 * VOX;
            const float* nzbase = g_z + (size_t)nn * (16 * VOX);
#pragma unroll
            for (int it = 0; it < 14; it++) {
                int idx = tid + it * 256;
                rv[it] = (idx < REG_N) ? region_val(idx, nh, nw0, nbase_t) : 0.f;
            }
#pragma unroll
            for (int it = 0; it < 7; it++) {
                int idx = tid + it * 256;
                zv[it] = (idx < 1632) ? z_val(idx, nh, nw0, nzbase)
                                      : make_float4(0.f, 0.f, 0.f, 0.f);
            }
        }

        // ---- MMA phase ----
        float acc[14][4];
#pragma unroll
        for (int t = 0; t < 14; t++)
#pragma unroll
            for (int q = 0; q < 4; q++) acc[t][q] = 0.f;

#pragma unroll
        for (int chunk = 0; chunk < 14; chunk++) {
            const u16* tp = s_tap + chunk * 16;
            int t0 = tp[2 * tc], t1 = tp[2 * tc + 1];
            int t2k = tp[8 + 2 * tc], t3 = tp[9 + 2 * tc];
            u32 aa[4];
            aa[0] = h2pack(region[t0 + aoffA], region[t1 + aoffA]);
            aa[1] = h2pack(region[t0 + aoffB], region[t1 + aoffB]);
            aa[2] = h2pack(region[t2k + aoffA], region[t3 + aoffA]);
            aa[3] = h2pack(region[t2k + aoffB], region[t3 + aoffB]);

#pragma unroll
            for (int nt = 0; nt < 14; nt++) {
                if (nt >= nts) break;
                int ntg = warp_n * 14 + nt;
                uint2 wf = *(const uint2*)(smem + W_OFF +
                                           ((chunk * 27 + ntg) * 32 + lane) * 8);
                MMA_F16(acc[nt], aa, wf.x, wf.y);
            }
        }

        // epilogue: acc + bias -> enc_s [grp][vox*4 + j]
#pragma unroll
        for (int nt = 0; nt < 14; nt++) {
            if (nt >= nts) break;
            int ntg = warp_n * 14 + nt;
            int oc = ntg * 8 + tc * 2;
            float bx = __ldg(b_enc + oc), by = __ldg(b_enc + oc + 1);
            int grp = ntg * 2 + (tc >> 1);
            int j = (tc & 1) * 2;
            int v0l = warp_m * 16 + g;
            float* ep = enc_s + grp * ENC_STRIDE + v0l * 4 + j;
            *(float2*)ep = make_float2(acc[nt][0] + bx, acc[nt][1] + by);
            *(float2*)(ep + 32) = make_float2(acc[nt][2] + bx, acc[nt][3] + by);
        }
        __syncthreads();           // enc_s ready

        // ---- out phase ----
        ull oacc[8][2];
#pragma unroll
        for (int c8 = 0; c8 < 8; c8++) { oacc[c8][0] = 0ull; oacc[c8][1] = 0ull; }
        float Z0 = 0.f, Z1 = 0.f, Z2 = 0.f, Z3 = 0.f;

#pragma unroll
        for (int k = 0; k < 27; k++) {
            const int thp = k / 9;
            const int twp = (k / 3) % 3;
            const int tdp = k % 3;
            const float* zp = zs + (((thp * 4) + wv + twp) * 34 + dv + tdp) * 20 + cgh * 8;

            float4 e = *(const float4*)(enc_s + (k * 2 + qh2) * ENC_STRIDE + vloc * 4);
            float p0 = __expf(e.x), p1 = __expf(e.y), p2 = __expf(e.z), p3 = __expf(e.w);
            Z0 += p0; Z1 += p1; Z2 += p2; Z3 += p3;
            ull kr0 = pack2(p0, p1), kr1 = pack2(p2, p3);

            float4 zq0 = *(const float4*)zp;
            float4 zq1 = *(const float4*)(zp + 4);
            float zsv[8] = { zq0.x, zq0.y, zq0.z, zq0.w, zq1.x, zq1.y, zq1.z, zq1.w };
#pragma unroll
            for (int c8 = 0; c8 < 8; c8++) {
                ull zz = dup2(zsv[c8]);
                oacc[c8][0] = ffma2(kr0, zz, oacc[c8][0]);
                oacc[c8][1] = ffma2(kr1, zz, oacc[c8][1]);
            }
        }

        ull iz0 = pack2(1.f / Z0, 1.f / Z1);
        ull iz1 = pack2(1.f / Z2, 1.f / Z3);

        int d = dv, w = w0 + wv;
#pragma unroll
        for (int c8 = 0; c8 < 8; c8++) {
            int c = cgh * 8 + c8;
            ull b2 = dup2(bo[c8]);
            int cbase = (n * 16 + c) * 64;
#pragma unroll
            for (int jq = 0; jq < 2; jq++) {
                ull res = ffma2(jq ? oacc[c8][1] : oacc[c8][0], jq ? iz1 : iz0, b2);
                int addr = (((cbase + h * 2 + qh2) * 64) + (w * 2 + jq)) * 64 + d * 2;
                *(ull*)(out + addr) = res;
            }
        }
    }
}

extern "C" void kernel_launch(void* const* d_in, const int* in_sizes, int n_in,
                              void* d_out, int out_size) {
    const float* x      = (const float*)d_in[0];
    const float* w_down = (const float*)d_in[1];
    const float* b_down = (const float*)d_in[2];
    const float* w_enc  = (const float*)d_in[3];
    const float* b_enc  = (const float*)d_in[4];
    const float* w_out  = (const float*)d_in[5];
    const float* b_out  = (const float*)d_in[6];
    float* out = (float*)d_out;

    cudaFuncSetAttribute(k_main, cudaFuncAttributeMaxDynamicSharedMemorySize, SMEM_MAIN);

    k_prep<<<48, 256>>>(w_enc);
    k_down<<<GV_TOTAL / 256, 256>>>(x, w_down, b_down, w_out);
    k_main<<<148, 256, SMEM_MAIN>>>(b_enc, b_out, out);
}

// round 13
// speedup vs baseline: 1.4701x; 1.4701x over previous
#include <cuda_runtime.h>
#include <cuda_fp16.h>
#include <cstdint>

// CARAFE3D: x[2,32,32,32,32] -> out[2,16,64,64,64]
//   k_init: blocks 0..255: t = W_down@x + b_down, z = W_out@x ([n][c/4][loc][4]);
//           blocks 256..303: W_enc -> fp16 mma-fragment-major + tap tables
//   k_enc : persistent, 2 CTA/SM; W resident; per-tile smem im2col region with
//           register prefetch; barrier-free fp16 mma.sync mainloop
//   k_out : q-split softmax + reassembly + pixel shuffle + b_out (vector loads)
typedef unsigned long long ull;
typedef unsigned int u32;
typedef unsigned short u16;

#define VOX 32768
#define GV_TOTAL 65536
#define NTILES 1024            // 64 voxels per tile (k_enc)

__device__ float g_t[2 * 8 * VOX];
__device__ __align__(16) float g_z[2 * 16 * VOX];        // [n][c/4][loc][4]
__device__ __align__(16) uint2 g_wfrag[12096];           // [chunk14][ntg27][lane32]
__device__ u16 g_tapoff[224];

#define REG_N 3352             // region floats (3264 data + zero tail)

__device__ __forceinline__ ull dup2(float a) {
    ull r; unsigned u = __float_as_uint(a);
    asm("mov.b64 %0, {%1, %1};" : "=l"(r) : "r"(u));
    return r;
}
__device__ __forceinline__ ull pack2(float a, float b) {
    ull r;
    asm("mov.b64 %0, {%1, %2};" : "=l"(r) : "r"(__float_as_uint(a)), "r"(__float_as_uint(b)));
    return r;
}
__device__ __forceinline__ ull ffma2(ull a, ull b, ull c) {
    ull d;
    asm("fma.rn.f32x2 %0, %1, %2, %3;" : "=l"(d) : "l"(a), "l"(b), "l"(c));
    return d;
}
#define MMA_F16(d, a, b0_, b1_) \
    asm volatile("mma.sync.aligned.m16n8k16.row.col.f32.f16.f16.f32 " \
        "{%0,%1,%2,%3}, {%4,%5,%6,%7}, {%8,%9}, {%0,%1,%2,%3};" \
        : "+f"((d)[0]), "+f"((d)[1]), "+f"((d)[2]), "+f"((d)[3]) \
        : "r"((a)[0]), "r"((a)[1]), "r"((a)[2]), "r"((a)[3]), "r"(b0_), "r"(b1_))

__device__ __forceinline__ unsigned short f16bits(float v) {
    __half h = __float2half_rn(v);
    return *(unsigned short*)&h;
}
__device__ __forceinline__ u32 h2pack(float a, float b) {
    __half2 h = __floats2half2_rn(a, b);     // low = a
    return *(u32*)&h;
}

// ---------------- k_init: down projections (blocks 0..255) + W prep (256..303) ----
__global__ __launch_bounds__(256) void k_init(
    const float* __restrict__ x,
    const float* __restrict__ wd, const float* __restrict__ bd,
    const float* __restrict__ wo,
    const float* __restrict__ w_enc)
{
    int tid = threadIdx.x;
    if (blockIdx.x >= 256) {
        // ---- prep branch ----
        int i = (blockIdx.x - 256) * 256 + tid;
        if (i < 12096) {
            int chunk = i / 864;
            int rem = i - chunk * 864;
            int ntg = rem >> 5;               // 0..26
            int lane = rem & 31;
            int g = lane >> 2, tc = lane & 3;
            int oc = ntg * 8 + g;
            int kb = chunk * 16;
            int ks[4] = { kb + 2 * tc, kb + 2 * tc + 1, kb + 8 + 2 * tc, kb + 9 + 2 * tc };
            unsigned short hh[4];
#pragma unroll
            for (int j = 0; j < 4; j++) {
                float v = (ks[j] < 216) ? w_enc[oc * 216 + ks[j]] : 0.f;
                hh[j] = f16bits(v);
            }
            uint2 q;
            q.x = (u32)hh[0] | ((u32)hh[1] << 16);
            q.y = (u32)hh[2] | ((u32)hh[3] << 16);
            g_wfrag[i] = q;
        }
        if (i < 224) {
            if (i < 216) {
                int ci = i / 27;
                int tap = i - ci * 27;
                int th = tap / 9;
                int tr = tap - th * 9;
                int tw = tr / 3;
                int td = tr - tw * 3;
                g_tapoff[i] = (u16)((((ci * 3 + th) * 4 + tw) * 34) + td);
            } else {
                g_tapoff[i] = (u16)3264;
            }
        }
        return;
    }

    // ---- down branch ----
    __shared__ float swd[8 * 32];
    __shared__ float swo[16 * 32];
    if (tid < 256) swd[tid] = wd[tid];
    swo[tid] = wo[tid];
    swo[tid + 256] = wo[tid + 256];
    __syncthreads();

    int gv = blockIdx.x * 256 + tid;
    int n = gv >> 15;
    int loc = gv & (VOX - 1);
    const float* xb = x + n * (32 * VOX) + loc;

    float xv[32];
#pragma unroll
    for (int c = 0; c < 32; c++) xv[c] = xb[c * VOX];
#pragma unroll
    for (int m = 0; m < 8; m++) {
        float acc = bd[m];
#pragma unroll
        for (int c = 0; c < 32; c++) acc += swd[m * 32 + c] * xv[c];
        g_t[(n * 8 + m) * VOX + loc] = acc;
    }
    float za[16];
#pragma unroll
    for (int m = 0; m < 16; m++) {
        float acc = 0.f;
#pragma unroll
        for (int c = 0; c < 32; c++) acc += swo[m * 32 + c] * xv[c];
        za[m] = acc;
    }
#pragma unroll
    for (int cg = 0; cg < 4; cg++)
        *(float4*)(g_z + ((size_t)(n * 4 + cg) * VOX + loc) * 4) =
            make_float4(za[cg * 4], za[cg * 4 + 1], za[cg * 4 + 2], za[cg * 4 + 3]);
}

// ---------------- k_enc: persistent, region-based, barrier-free mainloop ---------
#define W_OFF 0
#define REGION_OFF 96768
#define TAP_OFF 110176
#define SMEM_ENC 110720

__device__ float g_enc[(size_t)216 * GV_TOTAL];          // [54 grp][gv][4]

__device__ __forceinline__ float region_val(int idx, int h, int w0, int base_t) {
    if (idx >= 3264) return 0.f;
    int ci = idx / 408;
    int r1 = idx - ci * 408;
    int hh = r1 / 136;
    int r2 = r1 - hh * 136;
    int ww = r2 / 34;
    int dd = r2 - ww * 34;
    int hs = h + hh - 1, ws = w0 + ww - 1, ds = dd - 1;
    if ((unsigned)hs < 32u && (unsigned)ws < 32u && (unsigned)ds < 32u)
        return g_t[base_t + ci * VOX + (hs << 10) + (ws << 5) + ds];
    return 0.f;
}

__global__ __launch_bounds__(256, 2) void k_enc(const float* __restrict__ b_enc) {
    extern __shared__ __align__(16) char smem[];
    float* region = (float*)(smem + REGION_OFF);
    const u16* s_tap = (const u16*)(smem + TAP_OFF);
    int tid = threadIdx.x;

    {
        uint2* wdst = (uint2*)(smem + W_OFF);
        for (int i = tid; i < 12096; i += 256) wdst[i] = g_wfrag[i];
    }
    if (tid < 224) ((u16*)(smem + TAP_OFF))[tid] = g_tapoff[tid];

    int warp = tid >> 5, lane = tid & 31;
    int warp_m = warp & 3;
    int warp_n = warp >> 2;
    int g = lane >> 2, tc = lane & 3;
    int nts = warp_n ? 13 : 14;

    int vA = warp_m * 16 + g;
    int vB = vA + 8;
    int aoffA = (vA >> 5) * 34 + (vA & 31);
    int aoffB = (vB >> 5) * 34 + (vB & 31);

    int tile = blockIdx.x;
    float rv[14];
    {
        int h = ((tile * 64) & (VOX - 1)) >> 10;
        int w0 = ((tile * 64) >> 5) & 31;
        int base_t = (tile >= 512) ? 8 * VOX : 0;
#pragma unroll
        for (int it = 0; it < 14; it++) {
            int idx = tid + it * 256;
            rv[it] = (idx < REG_N) ? region_val(idx, h, w0, base_t) : 0.f;
        }
    }

    for (; tile < NTILES; tile += gridDim.x) {
        int gv0 = tile * 64;
        __syncthreads();
#pragma unroll
        for (int it = 0; it < 14; it++) {
            int idx = tid + it * 256;
            if (idx < REG_N) region[idx] = rv[it];
        }
        __syncthreads();

        int ntile = tile + gridDim.x;
        if (ntile < NTILES) {
            int h = ((ntile * 64) & (VOX - 1)) >> 10;
            int w0 = ((ntile * 64) >> 5) & 31;
            int base_t = (ntile >= 512) ? 8 * VOX : 0;
#pragma unroll
            for (int it = 0; it < 14; it++) {
                int idx = tid + it * 256;
                rv[it] = (idx < REG_N) ? region_val(idx, h, w0, base_t) : 0.f;
            }
        }

        float acc[14][4];
#pragma unroll
        for (int t = 0; t < 14; t++)
#pragma unroll
            for (int q = 0; q < 4; q++) acc[t][q] = 0.f;

#pragma unroll
        for (int chunk = 0; chunk < 14; chunk++) {
            const u16* tp = s_tap + chunk * 16;
            int t0 = tp[2 * tc], t1 = tp[2 * tc + 1];
            int t2 = tp[8 + 2 * tc], t3 = tp[9 + 2 * tc];
            u32 aa[4];
            aa[0] = h2pack(region[t0 + aoffA], region[t1 + aoffA]);
            aa[1] = h2pack(region[t0 + aoffB], region[t1 + aoffB]);
            aa[2] = h2pack(region[t2 + aoffA], region[t3 + aoffA]);
            aa[3] = h2pack(region[t2 + aoffB], region[t3 + aoffB]);

#pragma unroll
            for (int nt = 0; nt < 14; nt++) {
                if (nt >= nts) break;
                int ntg = warp_n * 14 + nt;
                uint2 wf = *(const uint2*)(smem + W_OFF +
                                           ((chunk * 27 + ntg) * 32 + lane) * 8);
                MMA_F16(acc[nt], aa, wf.x, wf.y);
            }
        }

#pragma unroll
        for (int nt = 0; nt < 14; nt++) {
            if (nt >= nts) break;
            int ntg = warp_n * 14 + nt;
            int oc = ntg * 8 + tc * 2;
            float bx = __ldg(b_enc + oc), by = __ldg(b_enc + oc + 1);
            int grp = ntg * 2 + (tc >> 1);
            int j = (tc & 1) * 2;
            int v0 = gv0 + warp_m * 16 + g;
            float* p = g_enc + ((size_t)grp * GV_TOTAL + v0) * 4 + j;
            *(float2*)p = make_float2(acc[nt][0] + bx, acc[nt][1] + by);
            *(float2*)(p + 32) = make_float2(acc[nt][2] + bx, acc[nt][3] + by);
        }
    }
}

// ---------------- k_out: q-split + vectorized coalesced loads ----------------
__global__ __launch_bounds__(256, 2) void k_out(const float* __restrict__ b_out,
                                                float* __restrict__ out)
{
    int tid = threadIdx.x;
    int vloc = tid & 127;
    int qh = tid >> 7;
    int gv = blockIdx.x * 128 + vloc;
    int n = gv >> 15;
    int loc = gv & (VOX - 1);
    int h = loc >> 10, w = (loc >> 5) & 31, d = loc & 31;

    const float* zb = g_z + (size_t)n * (16 * VOX);
    const float* eb = g_enc + ((size_t)qh * GV_TOTAL + gv) * 4;

    ull acc[16][2];
#pragma unroll
    for (int c = 0; c < 16; c++) { acc[c][0] = 0ull; acc[c][1] = 0ull; }
    float Z0 = 0.f, Z1 = 0.f, Z2 = 0.f, Z3 = 0.f;

#pragma unroll
    for (int k = 0; k < 27; k++) {
        const int th = k / 9 - 1;
        const int tw = (k / 3) % 3 - 1;
        const int td = k % 3 - 1;
        int hh = h + th, ww = w + tw, dd = d + td;
        bool ok = ((unsigned)hh < 32u) && ((unsigned)ww < 32u) && ((unsigned)dd < 32u);
        int zloc = (hh << 10) + (ww << 5) + dd;

        float4 e = __ldg((const float4*)(eb + (size_t)(k * 2) * GV_TOTAL * 4));
        float p0 = __expf(e.x), p1 = __expf(e.y), p2 = __expf(e.z), p3 = __expf(e.w);
        Z0 += p0; Z1 += p1; Z2 += p2; Z3 += p3;
        ull kr0 = pack2(p0, p1), kr1 = pack2(p2, p3);

#pragma unroll
        for (int cg = 0; cg < 4; cg++) {
            float4 zq;
            if (ok) zq = __ldg((const float4*)(zb + ((size_t)cg * VOX + zloc) * 4));
            else    zq = make_float4(0.f, 0.f, 0.f, 0.f);
            float zs[4] = { zq.x, zq.y, zq.z, zq.w };
#pragma unroll
            for (int u = 0; u < 4; u++) {
                int c = cg * 4 + u;
                ull zz = dup2(zs[u]);
                acc[c][0] = ffma2(kr0, zz, acc[c][0]);
                acc[c][1] = ffma2(kr1, zz, acc[c][1]);
            }
        }
    }

    ull iz0 = pack2(1.f / Z0, 1.f / Z1);
    ull iz1 = pack2(1.f / Z2, 1.f / Z3);

#pragma unroll
    for (int c = 0; c < 16; c++) {
        ull b2 = dup2(b_out[c]);
        int cbase = (n * 16 + c) * 64;
#pragma unroll
        for (int jq = 0; jq < 2; jq++) {
            int q = qh * 2 + jq;
            int rh = q >> 1, rw = q & 1;
            ull res = ffma2(jq ? acc[c][1] : acc[c][0], jq ? iz1 : iz0, b2);
            int addr = (((cbase + h * 2 + rh) * 64) + (w * 2 + rw)) * 64 + d * 2;
            *(ull*)(out + addr) = res;
        }
    }
}

extern "C" void kernel_launch(void* const* d_in, const int* in_sizes, int n_in,
                              void* d_out, int out_size) {
    const float* x      = (const float*)d_in[0];
    const float* w_down = (const float*)d_in[1];
    const float* b_down = (const float*)d_in[2];
    const float* w_enc  = (const float*)d_in[3];
    const float* b_enc  = (const float*)d_in[4];
    const float* w_out  = (const float*)d_in[5];
    const float* b_out  = (const float*)d_in[6];
    float* out = (float*)d_out;

    cudaFuncSetAttribute(k_enc, cudaFuncAttributeMaxDynamicSharedMemorySize, SMEM_ENC);

    k_init<<<304, 256>>>(x, w_down, b_down, w_out, w_enc);
    k_enc<<<296, 256, SMEM_ENC>>>(b_enc);
    k_out<<<GV_TOTAL / 128, 256>>>(b_out, out);
}